// round 15
// baseline (speedup 1.0000x reference)
#include <cuda_runtime.h>
#include <cuda_bf16.h>
#include <cstdint>
#include <cstddef>

#define EPS_VAL 0.5f
typedef unsigned long long u64;
typedef unsigned int u32;

// ===================== helpers =====================
__device__ __forceinline__ u64 ffma2(u64 a, u64 b, u64 c) {
    u64 d;
    asm("fma.rn.f32x2 %0, %1, %2, %3;" : "=l"(d) : "l"(a), "l"(b), "l"(c));
    return d;
}
__device__ __forceinline__ float f2sum(u64 v) {
    return __uint_as_float((unsigned)(v & 0xffffffffu)) +
           __uint_as_float((unsigned)(v >> 32));
}
__device__ __forceinline__ void mma_bf16(float* d, const u32* a, u32 b0, u32 b1) {
    asm volatile(
        "mma.sync.aligned.m16n8k16.row.col.f32.bf16.bf16.f32 "
        "{%0,%1,%2,%3}, {%4,%5,%6,%7}, {%8,%9}, {%0,%1,%2,%3};"
        : "+f"(d[0]), "+f"(d[1]), "+f"(d[2]), "+f"(d[3])
        : "r"(a[0]), "r"(a[1]), "r"(a[2]), "r"(a[3]), "r"(b0), "r"(b1));
}
__device__ __forceinline__ void ldmx4(u32* r, u32 addr) {
    asm volatile("ldmatrix.sync.aligned.m8n8.x4.shared.b16 {%0,%1,%2,%3}, [%4];"
        : "=r"(r[0]), "=r"(r[1]), "=r"(r[2]), "=r"(r[3]) : "r"(addr));
}
__device__ __forceinline__ u32 smem_u32(const void* p) {
    u32 a;
    asm("{ .reg .u64 t; cvta.to.shared.u64 t, %1; cvt.u32.u64 %0, t; }"
        : "=r"(a) : "l"(p));
    return a;
}
__device__ __forceinline__ u32 pack_bf16x2(__nv_bfloat16 lo, __nv_bfloat16 hi) {
    return (u32)__bfloat16_as_ushort(lo) | ((u32)__bfloat16_as_ushort(hi) << 16);
}
#define BAR_SYNC(id)   asm volatile("bar.sync %0, 768;"   :: "r"(id) : "memory")
#define BAR_ARRIVE(id) asm volatile("bar.arrive %0, 768;" :: "r"(id) : "memory")

// Scratch: node projections y [N_MAX, 256] fp32
#define N_MAX 100000
__device__ float g_y[(size_t)N_MAX * 256];

// ---------------------------------------------------------------------------
// Kernel 1: y = x @ W1^T + 0.5*b1  (SIMT fp32 f32x2 — exact; unchanged)
// ---------------------------------------------------------------------------
__global__ __launch_bounds__(256) void node_proj_kernel(
    const float* __restrict__ x, const float* __restrict__ W1,
    const float* __restrict__ b1, int N)
{
    extern __shared__ __align__(16) float sm[];
    float* xs = sm;
    float* ws = sm + 64 * 132;
    float* __restrict__ y = g_y;

    const int tid = threadIdx.x;
    const int n0 = blockIdx.x * 64;
    const int j0 = blockIdx.y * 64;

    #pragma unroll
    for (int it = 0; it < 8; it++) {
        int idx = tid + it * 256;
        int r = idx >> 5, c = (idx & 31) << 2;
        int gr = n0 + r;
        float4 v = make_float4(0.f, 0.f, 0.f, 0.f);
        if (gr < N) v = *(const float4*)(x + (size_t)gr * 128 + c);
        *(float4*)(xs + r * 132 + c) = v;
    }
    #pragma unroll
    for (int it = 0; it < 8; it++) {
        int idx = tid + it * 256;
        int r = idx >> 5, c = (idx & 31) << 2;
        float4 v = *(const float4*)(W1 + (size_t)(j0 + r) * 128 + c);
        *(float4*)(ws + r * 132 + c) = v;
    }
    __syncthreads();

    const int l = tid & 31, w = tid >> 5;
    const int le = l >> 3, lo = l & 7;
    const int we = w & 3,  wo = w >> 2;

    u64 acc[4][4];
    #pragma unroll
    for (int i = 0; i < 4; i++)
        #pragma unroll
        for (int r = 0; r < 4; r++) acc[i][r] = 0ull;

    const float* xbase = xs + (16 * we + le) * 132;
    const float* wbase = ws + (32 * wo + lo) * 132;

    #pragma unroll 2
    for (int k = 0; k < 128; k += 4) {
        ulonglong2 xa[4], wb[4];
        #pragma unroll
        for (int i = 0; i < 4; i++) xa[i] = *(const ulonglong2*)(xbase + (4 * i) * 132 + k);
        #pragma unroll
        for (int r = 0; r < 4; r++) wb[r] = *(const ulonglong2*)(wbase + (8 * r) * 132 + k);
        #pragma unroll
        for (int i = 0; i < 4; i++)
            #pragma unroll
            for (int r = 0; r < 4; r++) {
                acc[i][r] = ffma2(xa[i].x, wb[r].x, acc[i][r]);
                acc[i][r] = ffma2(xa[i].y, wb[r].y, acc[i][r]);
            }
    }
    __syncthreads();

    float* stage = sm;
    #pragma unroll
    for (int i = 0; i < 4; i++)
        #pragma unroll
        for (int r = 0; r < 4; r++) {
            int rl = 16 * we + le + 4 * i;
            int cl = 32 * wo + lo + 8 * r;
            stage[rl * 68 + cl] = f2sum(acc[i][r]) + 0.5f * b1[j0 + cl];
        }
    __syncthreads();

    #pragma unroll
    for (int it = 0; it < 4; it++) {
        int idx = tid + it * 256;
        int r = idx >> 4, c = (idx & 15) << 2;
        int gr = n0 + r;
        if (gr < N)
            *(float4*)(y + (size_t)gr * 256 + j0 + c) = *(float4*)(stage + r * 68 + c);
    }
}

// ---------------------------------------------------------------------------
// Kernel 2: warp-specialized persistent edge GEMM (scaled-up R7).
// 768 threads: warps 0-15 consumers (4m x 4n, each m32n32 over M=128 x N=128),
// warps 16-23 producers (256 threads, 2 per edge row).
// K=256 in 4 chunks of 64; h chunk buffers 2-deep.
// D = Ahi*Bhi + Ahi*Blo + Alo*Bhi  (fp32 accum)
// Named barriers (count 768): full[buf]=1+buf, empty[buf]=3+buf, buf=g&1.
// ---------------------------------------------------------------------------
// smem: W2hi [128][264]bf16 (67584), W2lo (67584),
//       2 x h-chunk buf: hi [128 rows][72 bf16] (18432) + lo (18432) = 36864
//       row stride 144 B (36 words == 4 mod 32 -> conflict-free ldmatrix/STS)
//       b2 (pre-scaled) 512 B at the end.
#define SM_WHI 0
#define SM_WLO 67584
#define SM_H   135168
#define HBUF   36864
#define HHALF  18432
#define HSTRIDE 144
#define SM_B2  (135168 + 2 * 36864)      // 208896
#define SMEM_EDGE (208896 + 512)         // 209408 B

__global__ __launch_bounds__(768, 1) void edge_mma_kernel(
    const int* __restrict__ edge_index,
    const float* __restrict__ W2, const float* __restrict__ b2,
    float* __restrict__ out, int E)
{
    extern __shared__ __align__(16) char smem[];
    const float* __restrict__ y = g_y;
    const u32 sbase = smem_u32(smem);

    const int tid  = threadIdx.x;
    const int lane = tid & 31;
    const int wid  = tid >> 5;

    // --- one-time: W2 hi/lo split + scaled b2 into smem (all threads) ---
    if (tid < 128) *(float*)(smem + SM_B2 + tid * 4) = b2[tid] * EPS_VAL;
    for (int idx = tid; idx < 128 * 256; idx += 768) {
        int n = idx >> 8, k = idx & 255;
        float w = W2[idx];
        __nv_bfloat16 hb = __float2bfloat16(w);
        __nv_bfloat16 lb = __float2bfloat16(w - __bfloat162float(hb));
        u32 byte = (u32)n * 528u + (u32)k * 2u;
        *(__nv_bfloat16*)(smem + SM_WHI + byte) = hb;
        *(__nv_bfloat16*)(smem + SM_WLO + byte) = lb;
    }
    __syncthreads();

    const int ntiles = (E + 127) / 128;

    if (wid < 16) {
        // ===== CONSUMERS: 16 warps, 4m x 4n, each m32 x n32 =====
        const int wm = wid & 3;       // 32-row group (0..3)
        const int wn = wid >> 2;      // 32-col group (0..3)

        const u32 aoff = (u32)(lane & 15) * HSTRIDE + (u32)(lane >> 4) * 16u;
        const u32 boff = ((u32)(lane & 7) + (u32)((lane >> 4) & 1) * 8u) * 528u
                       + (u32)((lane >> 3) & 1) * 16u;
        const u32 sa0 = sbase + SM_H + (u32)(wm * 32) * HSTRIDE + aoff;
        const u32 sbH = sbase + SM_WHI + (u32)(wn * 32) * 528u + boff;
        const u32 sbL = sbH + 67584u;

        int g = 0;
        for (int t = blockIdx.x; t < ntiles; t += gridDim.x) {
            float acc[2][4][4];
            #pragma unroll
            for (int mt = 0; mt < 2; mt++)
                #pragma unroll
                for (int j = 0; j < 4; j++)
                    #pragma unroll
                    for (int v = 0; v < 4; v++) acc[mt][j][v] = 0.f;

            for (int c = 0; c < 4; c++, g++) {
                const int buf = g & 1;
                BAR_SYNC(1 + buf);
                const u32 saH = sa0 + (u32)buf * HBUF;
                const u32 saL = saH + HHALF;

                #pragma unroll
                for (int ks = 0; ks < 4; ks++) {
                    const u32 ka = (u32)ks * 32u;         // k16 step in h row
                    const u32 kb = (u32)c * 128u + ka;    // k16 step in W2 row
                    u32 bH[8], bL[8];
                    ldmx4(bH,     sbH + kb);
                    ldmx4(bH + 4, sbH + 16u * 528u + kb);
                    ldmx4(bL,     sbL + kb);
                    ldmx4(bL + 4, sbL + 16u * 528u + kb);
                    #pragma unroll
                    for (int mt = 0; mt < 2; mt++) {
                        u32 aH[4], aL[4];
                        ldmx4(aH, saH + (u32)(mt * 16) * HSTRIDE + ka);
                        ldmx4(aL, saL + (u32)(mt * 16) * HSTRIDE + ka);
                        #pragma unroll
                        for (int j = 0; j < 4; j++) {
                            mma_bf16(acc[mt][j], aH, bH[2*j], bH[2*j+1]);
                            mma_bf16(acc[mt][j], aH, bL[2*j], bL[2*j+1]);
                            mma_bf16(acc[mt][j], aL, bH[2*j], bH[2*j+1]);
                        }
                    }
                }
                BAR_ARRIVE(3 + buf);
            }

            // epilogue: bias (pre-scaled) from smem
            const int t0 = t * 128;
            float bbx[4], bby[4];
            #pragma unroll
            for (int j = 0; j < 4; j++) {
                int col = wn * 32 + j * 8 + (lane & 3) * 2;
                bbx[j] = *(const float*)(smem + SM_B2 + col * 4);
                bby[j] = *(const float*)(smem + SM_B2 + (col + 1) * 4);
            }
            #pragma unroll
            for (int mt = 0; mt < 2; mt++)
                #pragma unroll
                for (int j = 0; j < 4; j++) {
                    int col = wn * 32 + j * 8 + (lane & 3) * 2;
                    int r0 = t0 + wm * 32 + mt * 16 + (lane >> 2);
                    if (r0 < E) {
                        float2 v;
                        v.x = fmaf(acc[mt][j][0], EPS_VAL, bbx[j]);
                        v.y = fmaf(acc[mt][j][1], EPS_VAL, bby[j]);
                        *(float2*)(out + (size_t)r0 * 128 + col) = v;
                    }
                    int r1 = r0 + 8;
                    if (r1 < E) {
                        float2 v;
                        v.x = fmaf(acc[mt][j][2], EPS_VAL, bbx[j]);
                        v.y = fmaf(acc[mt][j][3], EPS_VAL, bby[j]);
                        *(float2*)(out + (size_t)r1 * 128 + col) = v;
                    }
                }
        }
    } else {
        // ===== PRODUCERS: 8 warps (256 threads), 2 threads per edge row =====
        const int ptid = tid - 512;
        const int r  = ptid >> 1;     // edge row 0..127
        const int hf = ptid & 1;      // k32-half within the k64 chunk

        int g = 0;
        for (int t = blockIdx.x; t < ntiles; t += gridDim.x) {
            const int e = t * 128 + r;
            const bool valid = (e < E);
            int s = 0, dd = 0;
            if (valid) { s = edge_index[e]; dd = edge_index[E + e]; }
            const float* ys = y + (size_t)s  * 256 + hf * 32;
            const float* yd = y + (size_t)dd * 256 + hf * 32;
            char* hrow = smem + SM_H + r * HSTRIDE + hf * 64;

            for (int c = 0; c < 4; c++, g++) {
                const int buf = g & 1;
                if (g >= 2) BAR_SYNC(3 + buf);

                if (valid) {
                    char* hhi = hrow + buf * HBUF;
                    char* hlo = hhi + HHALF;
                    // 32 floats per node, processed in 2 halves of 16
                    #pragma unroll
                    for (int half = 0; half < 2; half++) {
                        float4 A[4], B[4];
                        #pragma unroll
                        for (int j = 0; j < 4; j++) {
                            A[j] = *(const float4*)(ys + c * 64 + half * 16 + 4 * j);
                            B[j] = *(const float4*)(yd + c * 64 + half * 16 + 4 * j);
                        }
                        u32 hi[8], lo[8];
                        #pragma unroll
                        for (int j = 0; j < 4; j++) {
                            float h0 = fmaxf(A[j].x + B[j].x, 0.f);
                            float h1 = fmaxf(A[j].y + B[j].y, 0.f);
                            float h2 = fmaxf(A[j].z + B[j].z, 0.f);
                            float h3 = fmaxf(A[j].w + B[j].w, 0.f);
                            __nv_bfloat16 p0 = __float2bfloat16(h0), p1 = __float2bfloat16(h1);
                            __nv_bfloat16 p2 = __float2bfloat16(h2), p3 = __float2bfloat16(h3);
                            hi[2*j]   = pack_bf16x2(p0, p1);
                            hi[2*j+1] = pack_bf16x2(p2, p3);
                            lo[2*j]   = pack_bf16x2(__float2bfloat16(h0 - __bfloat162float(p0)),
                                                    __float2bfloat16(h1 - __bfloat162float(p1)));
                            lo[2*j+1] = pack_bf16x2(__float2bfloat16(h2 - __bfloat162float(p2)),
                                                    __float2bfloat16(h3 - __bfloat162float(p3)));
                        }
                        *(uint4*)(hhi + half * 32)      = make_uint4(hi[0], hi[1], hi[2], hi[3]);
                        *(uint4*)(hhi + half * 32 + 16) = make_uint4(hi[4], hi[5], hi[6], hi[7]);
                        *(uint4*)(hlo + half * 32)      = make_uint4(lo[0], lo[1], lo[2], lo[3]);
                        *(uint4*)(hlo + half * 32 + 16) = make_uint4(lo[4], lo[5], lo[6], lo[7]);
                    }
                }
                BAR_ARRIVE(1 + buf);
            }
        }
    }
}

// ---------------------------------------------------------------------------
extern "C" void kernel_launch(void* const* d_in, const int* in_sizes, int n_in,
                              void* d_out, int out_size) {
    const float* x  = (const float*)d_in[0];
    const int*   ei = (const int*)d_in[1];     // int32 [2, E]
    const float* W1 = (const float*)d_in[2];
    const float* b1 = (const float*)d_in[3];
    const float* W2 = (const float*)d_in[4];
    const float* b2 = (const float*)d_in[5];
    float* out = (float*)d_out;

    int N = in_sizes[0] / 128;
    int E = in_sizes[1] / 2;

    const int SMEM1 = 2 * 64 * 132 * sizeof(float);
    cudaFuncSetAttribute(node_proj_kernel,
                         cudaFuncAttributeMaxDynamicSharedMemorySize, SMEM1);
    cudaFuncSetAttribute(edge_mma_kernel,
                         cudaFuncAttributeMaxDynamicSharedMemorySize, SMEM_EDGE);

    dim3 g1((N + 63) / 64, 4);
    node_proj_kernel<<<g1, 256, SMEM1>>>(x, W1, b1, N);

    edge_mma_kernel<<<152, 768, SMEM_EDGE>>>(ei, W2, b2, out, E);
}

// round 16
// speedup vs baseline: 1.9887x; 1.9887x over previous
#include <cuda_runtime.h>
#include <cuda_bf16.h>
#include <cstdint>
#include <cstddef>

#define EPS_VAL 0.5f
typedef unsigned long long u64;
typedef unsigned int u32;

// ===================== helpers =====================
__device__ __forceinline__ void mma_bf16(float* d, const u32* a, u32 b0, u32 b1) {
    asm volatile(
        "mma.sync.aligned.m16n8k16.row.col.f32.bf16.bf16.f32 "
        "{%0,%1,%2,%3}, {%4,%5,%6,%7}, {%8,%9}, {%0,%1,%2,%3};"
        : "+f"(d[0]), "+f"(d[1]), "+f"(d[2]), "+f"(d[3])
        : "r"(a[0]), "r"(a[1]), "r"(a[2]), "r"(a[3]), "r"(b0), "r"(b1));
}
__device__ __forceinline__ void ldmx4(u32* r, u32 addr) {
    asm volatile("ldmatrix.sync.aligned.m8n8.x4.shared.b16 {%0,%1,%2,%3}, [%4];"
        : "=r"(r[0]), "=r"(r[1]), "=r"(r[2]), "=r"(r[3]) : "r"(addr));
}
__device__ __forceinline__ u32 smem_u32(const void* p) {
    u32 a;
    asm("{ .reg .u64 t; cvta.to.shared.u64 t, %1; cvt.u32.u64 %0, t; }"
        : "=r"(a) : "l"(p));
    return a;
}
// packed bf16x2 convert: r = {bf16(hi_f) , bf16(lo_f)}  (lo in bits 0-15)
__device__ __forceinline__ u32 cvt_bf16x2(float lo_f, float hi_f) {
    u32 r;
    asm("cvt.rn.bf16x2.f32 %0, %1, %2;" : "=r"(r) : "f"(hi_f), "f"(lo_f));
    return r;
}
#define BAR_SYNC(id)   asm volatile("bar.sync %0, 512;"   :: "r"(id) : "memory")
#define BAR_ARRIVE(id) asm volatile("bar.arrive %0, 512;" :: "r"(id) : "memory")

// Scratch: node projections y [N_MAX, 256] fp32
#define N_MAX 100000
__device__ float g_y[(size_t)N_MAX * 256];

// ---------------------------------------------------------------------------
// Kernel 1: y = x @ W1^T + 0.5*b1  — 3-term bf16 mma (persistent).
// 256 threads = 8 warps (2m x 4n, each m32 x n64). Tile M=64 x N=256, K=128.
// W1 hi/lo converted to smem once; x tile converted per tile.
// ---------------------------------------------------------------------------
// smem: Whi [256][136bf16] (69632), Wlo (69632), xhi [64][136] (17408),
//       xlo (17408), b1*0.5 (1024). Stride 272B = 17*16 (aligned, 68w==4 mod 32)
#define K1_WH 0
#define K1_WL 69632
#define K1_XH 139264
#define K1_XL (139264 + 17408)
#define K1_B1 (139264 + 2 * 17408)
#define SMEM1 (K1_B1 + 1024)             // 175104 B

__global__ __launch_bounds__(256, 1) void node_proj_kernel(
    const float* __restrict__ x, const float* __restrict__ W1,
    const float* __restrict__ b1, int N)
{
    extern __shared__ __align__(16) char smem[];
    const u32 sbase = smem_u32(smem);
    float* __restrict__ y = g_y;

    const int tid  = threadIdx.x;
    const int lane = tid & 31;
    const int wid  = tid >> 5;
    const int wm = wid & 1;       // 32-row group
    const int wn = wid >> 1;      // 64-col group (0..3)

    // one-time: b1*0.5 + W1 hi/lo split
    if (tid < 256) *(float*)(smem + K1_B1 + tid * 4) = 0.5f * b1[tid];
    for (int idx = tid; idx < 256 * 128; idx += 256) {
        int n = idx >> 7, k = idx & 127;
        float w = W1[idx];
        __nv_bfloat16 hb = __float2bfloat16(w);
        float hf = __bfloat162float(hb);
        u32 byte = (u32)n * 272u + (u32)k * 2u;
        *(__nv_bfloat16*)(smem + K1_WH + byte) = hb;
        *(__nv_bfloat16*)(smem + K1_WL + byte) = __float2bfloat16(w - hf);
    }

    const u32 aoff = (u32)(lane & 15) * 272u + (u32)(lane >> 4) * 16u;
    const u32 boff = ((u32)(lane & 7) + (u32)((lane >> 4) & 1) * 8u) * 272u
                   + (u32)((lane >> 3) & 1) * 16u;
    const u32 saH = sbase + K1_XH + (u32)(wm * 32) * 272u + aoff;
    const u32 saL = saH + 17408u;
    const u32 sb0 = sbase + K1_WH + (u32)(wn * 64) * 272u + boff;

    const int ntiles = (N + 63) / 64;
    for (int t = blockIdx.x; t < ntiles; t += gridDim.x) {
        const int t0 = t * 64;
        __syncthreads();   // xs free (previous tile's mma done)

        // load + split x tile [64][128]
        #pragma unroll
        for (int it = 0; it < 8; it++) {
            int idx = tid + it * 256;
            int r = idx >> 5, c4 = (idx & 31) << 2;
            int gr = t0 + r;
            float4 v = make_float4(0.f, 0.f, 0.f, 0.f);
            if (gr < N) v = *(const float4*)(x + (size_t)gr * 128 + c4);
            u32 hi01 = cvt_bf16x2(v.x, v.y);
            u32 hi23 = cvt_bf16x2(v.z, v.w);
            float f0 = __uint_as_float(hi01 << 16);
            float f1 = __uint_as_float(hi01 & 0xffff0000u);
            float f2 = __uint_as_float(hi23 << 16);
            float f3 = __uint_as_float(hi23 & 0xffff0000u);
            u32 lo01 = cvt_bf16x2(v.x - f0, v.y - f1);
            u32 lo23 = cvt_bf16x2(v.z - f2, v.w - f3);
            u32 byte = (u32)r * 272u + (u32)c4 * 2u;
            *(uint2*)(smem + K1_XH + byte) = make_uint2(hi01, hi23);
            *(uint2*)(smem + K1_XL + byte) = make_uint2(lo01, lo23);
        }
        __syncthreads();

        float acc[2][8][4];
        #pragma unroll
        for (int mt = 0; mt < 2; mt++)
            #pragma unroll
            for (int j = 0; j < 8; j++)
                #pragma unroll
                for (int v = 0; v < 4; v++) acc[mt][j][v] = 0.f;

        #pragma unroll 2
        for (int ks = 0; ks < 8; ks++) {
            const u32 ka = (u32)ks * 32u;
            u32 aH[2][4], aL[2][4];
            ldmx4(aH[0], saH + ka);
            ldmx4(aH[1], saH + 16u * 272u + ka);
            ldmx4(aL[0], saL + ka);
            ldmx4(aL[1], saL + 16u * 272u + ka);
            #pragma unroll
            for (int jj = 0; jj < 4; jj++) {
                u32 bH[4], bL[4];
                ldmx4(bH, sb0 + (u32)(jj * 16) * 272u + ka);
                ldmx4(bL, sb0 + 69632u + (u32)(jj * 16) * 272u + ka);
                #pragma unroll
                for (int mt = 0; mt < 2; mt++)
                    #pragma unroll
                    for (int jb = 0; jb < 2; jb++) {
                        mma_bf16(acc[mt][jj*2+jb], aH[mt], bH[2*jb], bH[2*jb+1]);
                        mma_bf16(acc[mt][jj*2+jb], aH[mt], bL[2*jb], bL[2*jb+1]);
                        mma_bf16(acc[mt][jj*2+jb], aL[mt], bH[2*jb], bH[2*jb+1]);
                    }
            }
        }

        // epilogue: y = acc + 0.5*b1
        #pragma unroll
        for (int mt = 0; mt < 2; mt++)
            #pragma unroll
            for (int j = 0; j < 8; j++) {
                int col = wn * 64 + j * 8 + (lane & 3) * 2;
                float bb0 = *(const float*)(smem + K1_B1 + col * 4);
                float bb1 = *(const float*)(smem + K1_B1 + (col + 1) * 4);
                int r0 = t0 + wm * 32 + mt * 16 + (lane >> 2);
                if (r0 < N) {
                    float2 v;
                    v.x = acc[mt][j][0] + bb0;
                    v.y = acc[mt][j][1] + bb1;
                    *(float2*)(y + (size_t)r0 * 256 + col) = v;
                }
                int r1 = r0 + 8;
                if (r1 < N) {
                    float2 v;
                    v.x = acc[mt][j][2] + bb0;
                    v.y = acc[mt][j][3] + bb1;
                    *(float2*)(y + (size_t)r1 * 256 + col) = v;
                }
            }
    }
}

// ---------------------------------------------------------------------------
// Kernel 2: warp-specialized persistent edge GEMM (R7 structure, proven).
// 512 threads: warps 0-7 consumers (2m x 4n, m32n32 over M=64 x N=128),
// warps 8-15 producers. K=256 in 4 chunks of 64; h buffers 4-deep.
// D = Ahi*Bhi + Ahi*Blo + Alo*Bhi  (fp32 accum)
// Named barriers (count 512): full[buf]=1+buf, empty[buf]=5+buf, buf=g&3.
// Producer convert uses packed cvt.rn.bf16x2.f32 (~30% ALU cut vs R7).
// ---------------------------------------------------------------------------
#define SM_WHI 0
#define SM_WLO 67584
#define SM_H   135168
#define HBUF   18432
#define HHALF  9216
#define HSTRIDE 144
#define SMEM_EDGE (135168 + 4 * 18432)   // 208896 B

__global__ __launch_bounds__(512, 1) void edge_mma_kernel(
    const int* __restrict__ edge_index,
    const float* __restrict__ W2, const float* __restrict__ b2,
    float* __restrict__ out, int E)
{
    extern __shared__ __align__(16) char smem[];
    const float* __restrict__ y = g_y;
    const u32 sbase = smem_u32(smem);

    const int tid  = threadIdx.x;
    const int lane = tid & 31;
    const int wid  = tid >> 5;

    // --- one-time: W2 hi/lo split into smem (all threads) ---
    for (int idx = tid; idx < 128 * 256; idx += 512) {
        int n = idx >> 8, k = idx & 255;
        float w = W2[idx];
        __nv_bfloat16 hb = __float2bfloat16(w);
        __nv_bfloat16 lb = __float2bfloat16(w - __bfloat162float(hb));
        u32 byte = (u32)n * 528u + (u32)k * 2u;
        *(__nv_bfloat16*)(smem + SM_WHI + byte) = hb;
        *(__nv_bfloat16*)(smem + SM_WLO + byte) = lb;
    }
    __syncthreads();

    const int ntiles = (E + 63) / 64;

    if (wid < 8) {
        // ===== CONSUMERS: 8 warps, 2m x 4n, each m32 x n32 =====
        const int wm = wid & 1;
        const int wn = wid >> 1;

        const u32 aoff = (u32)(lane & 15) * HSTRIDE + (u32)(lane >> 4) * 16u;
        const u32 boff = ((u32)(lane & 7) + (u32)((lane >> 4) & 1) * 8u) * 528u
                       + (u32)((lane >> 3) & 1) * 16u;
        const u32 sa0 = sbase + SM_H + (u32)(wm * 32) * HSTRIDE + aoff;
        const u32 sbH = sbase + SM_WHI + (u32)(wn * 32) * 528u + boff;
        const u32 sbL = sbH + 67584u;

        float bbx[4], bby[4];
        #pragma unroll
        for (int j = 0; j < 4; j++) {
            int col = wn * 32 + j * 8 + (lane & 3) * 2;
            bbx[j] = b2[col] * EPS_VAL;
            bby[j] = b2[col + 1] * EPS_VAL;
        }

        int g = 0;
        for (int t = blockIdx.x; t < ntiles; t += gridDim.x) {
            float acc[2][4][4];
            #pragma unroll
            for (int mt = 0; mt < 2; mt++)
                #pragma unroll
                for (int j = 0; j < 4; j++)
                    #pragma unroll
                    for (int v = 0; v < 4; v++) acc[mt][j][v] = 0.f;

            for (int c = 0; c < 4; c++, g++) {
                const int buf = g & 3;
                BAR_SYNC(1 + buf);
                const u32 saH = sa0 + (u32)buf * HBUF;
                const u32 saL = saH + HHALF;

                #pragma unroll
                for (int ks = 0; ks < 4; ks++) {
                    const u32 ka = (u32)ks * 32u;
                    const u32 kb = (u32)c * 128u + ka;
                    u32 aH[2][4], aL[2][4], bH[8], bL[8];
                    ldmx4(aH[0], saH + ka);
                    ldmx4(aH[1], saH + 16u * HSTRIDE + ka);
                    ldmx4(aL[0], saL + ka);
                    ldmx4(aL[1], saL + 16u * HSTRIDE + ka);
                    ldmx4(bH,     sbH + kb);
                    ldmx4(bH + 4, sbH + 16u * 528u + kb);
                    ldmx4(bL,     sbL + kb);
                    ldmx4(bL + 4, sbL + 16u * 528u + kb);
                    #pragma unroll
                    for (int mt = 0; mt < 2; mt++)
                        #pragma unroll
                        for (int j = 0; j < 4; j++) {
                            mma_bf16(acc[mt][j], aH[mt], bH[2*j], bH[2*j+1]);
                            mma_bf16(acc[mt][j], aH[mt], bL[2*j], bL[2*j+1]);
                            mma_bf16(acc[mt][j], aL[mt], bH[2*j], bH[2*j+1]);
                        }
                }
                BAR_ARRIVE(5 + buf);
            }

            const int t0 = t * 64;
            #pragma unroll
            for (int mt = 0; mt < 2; mt++)
                #pragma unroll
                for (int j = 0; j < 4; j++) {
                    int col = wn * 32 + j * 8 + (lane & 3) * 2;
                    int r0 = t0 + wm * 32 + mt * 16 + (lane >> 2);
                    if (r0 < E) {
                        float2 v;
                        v.x = fmaf(acc[mt][j][0], EPS_VAL, bbx[j]);
                        v.y = fmaf(acc[mt][j][1], EPS_VAL, bby[j]);
                        *(float2*)(out + (size_t)r0 * 128 + col) = v;
                    }
                    int r1 = r0 + 8;
                    if (r1 < E) {
                        float2 v;
                        v.x = fmaf(acc[mt][j][2], EPS_VAL, bbx[j]);
                        v.y = fmaf(acc[mt][j][3], EPS_VAL, bby[j]);
                        *(float2*)(out + (size_t)r1 * 128 + col) = v;
                    }
                }
        }
    } else {
        // ===== PRODUCERS: 8 warps (256 threads), 4 threads per edge row =====
        const int ptid = tid - 256;
        const int r = ptid >> 2;      // edge row 0..63
        const int q = ptid & 3;       // 16-float sub-chunk

        int g = 0;
        for (int t = blockIdx.x; t < ntiles; t += gridDim.x) {
            const int e = t * 64 + r;
            const bool valid = (e < E);
            int s = 0, dd = 0;
            if (valid) { s = edge_index[e]; dd = edge_index[E + e]; }
            const float* ys = y + (size_t)s  * 256 + q * 16;
            const float* yd = y + (size_t)dd * 256 + q * 16;
            char* hrow = smem + SM_H + r * HSTRIDE + q * 32;

            for (int c = 0; c < 4; c++, g++) {
                const int buf = g & 3;
                if (g >= 4) BAR_SYNC(5 + buf);

                if (valid) {
                    float4 A[4], B[4];
                    #pragma unroll
                    for (int j = 0; j < 4; j++) {
                        A[j] = *(const float4*)(ys + c * 64 + 4 * j);
                        B[j] = *(const float4*)(yd + c * 64 + 4 * j);
                    }
                    u32 hi[8], lo[8];
                    #pragma unroll
                    for (int j = 0; j < 4; j++) {
                        float h0 = fmaxf(A[j].x + B[j].x, 0.f);
                        float h1 = fmaxf(A[j].y + B[j].y, 0.f);
                        float h2 = fmaxf(A[j].z + B[j].z, 0.f);
                        float h3 = fmaxf(A[j].w + B[j].w, 0.f);
                        u32 hi01 = cvt_bf16x2(h0, h1);
                        u32 hi23 = cvt_bf16x2(h2, h3);
                        float f0 = __uint_as_float(hi01 << 16);
                        float f1 = __uint_as_float(hi01 & 0xffff0000u);
                        float f2 = __uint_as_float(hi23 << 16);
                        float f3 = __uint_as_float(hi23 & 0xffff0000u);
                        hi[2*j]   = hi01;
                        hi[2*j+1] = hi23;
                        lo[2*j]   = cvt_bf16x2(h0 - f0, h1 - f1);
                        lo[2*j+1] = cvt_bf16x2(h2 - f2, h3 - f3);
                    }
                    char* hhi = hrow + buf * HBUF;
                    char* hlo = hhi + HHALF;
                    *(uint4*)(hhi)      = make_uint4(hi[0], hi[1], hi[2], hi[3]);
                    *(uint4*)(hhi + 16) = make_uint4(hi[4], hi[5], hi[6], hi[7]);
                    *(uint4*)(hlo)      = make_uint4(lo[0], lo[1], lo[2], lo[3]);
                    *(uint4*)(hlo + 16) = make_uint4(lo[4], lo[5], lo[6], lo[7]);
                }
                BAR_ARRIVE(1 + buf);
            }
        }
    }
}

// ---------------------------------------------------------------------------
extern "C" void kernel_launch(void* const* d_in, const int* in_sizes, int n_in,
                              void* d_out, int out_size) {
    const float* x  = (const float*)d_in[0];
    const int*   ei = (const int*)d_in[1];     // int32 [2, E]
    const float* W1 = (const float*)d_in[2];
    const float* b1 = (const float*)d_in[3];
    const float* W2 = (const float*)d_in[4];
    const float* b2 = (const float*)d_in[5];
    float* out = (float*)d_out;

    int N = in_sizes[0] / 128;
    int E = in_sizes[1] / 2;

    cudaFuncSetAttribute(node_proj_kernel,
                         cudaFuncAttributeMaxDynamicSharedMemorySize, SMEM1);
    cudaFuncSetAttribute(edge_mma_kernel,
                         cudaFuncAttributeMaxDynamicSharedMemorySize, SMEM_EDGE);

    node_proj_kernel<<<152, 256, SMEM1>>>(x, W1, b1, N);
    edge_mma_kernel<<<152, 512, SMEM_EDGE>>>(ei, W2, b2, out, E);
}